// round 14
// baseline (speedup 1.0000x reference)
#include <cuda_runtime.h>
#include <cuda_fp16.h>
#include <cstdint>
#include <math.h>

#define BATCH 262144
#define GD 16
#define HID 256
#define RR 16
#define ZD 128
#define MTILE 128
#define NBLK (BATCH / MTILE)

// ---- fused kernel dynamic smem layout (bytes) ----
#define OFF_XF   0        // x A-frags 4096         [ufA overlays]
#define OFF_W1F  4096     // W1 B-frags 8192
#define OFF_W3F  12288    // W3 B-frags 8192        [ufB overlays]
#define OFF_H1F  20480    // h1 A-frags 65536       [hp overlays]
#define OFF_W2F  86016    // W2 resident 8x16384 = 131072 [zs/cs/ds/lg overlay]
#define SMEM_BYTES 217088
// overlays
#define OFF_UFA  0             // 8192 (over XF+W1F)
#define OFF_UFB  12288         // 8192 (over W3F)
#define OFF_HP   20480         // 8*16*128*4 = 65536 (over H1F)
#define OFF_ZS   86016         // 128*132*4 = 67584
#define OFF_CS   153600        // 128*20*4  = 10240
#define OFF_DS   163840        // 128*20*4  = 10240
#define OFF_LG   174080        // 512

// device-global weight images (allocation-free scratch)
__device__ __align__(256) uint32_t g_wfrag[36864];  // W2 8x16KB, W1 @u32 32768, W3 @u32 34816
__device__ __align__(256) float g_ufA[2048];
__device__ __align__(256) float g_ufB[2048];

__device__ __forceinline__ uint32_t fbits(float x) { return __float_as_uint(x); }
__device__ __forceinline__ float nan0(float v) { return isfinite(v) ? v : 0.f; }
__device__ __forceinline__ uint32_t packh(float lo, float hi) {
    uint32_t u;
    asm("cvt.rn.f16x2.f32 %0, %1, %2;" : "=r"(u) : "f"(hi), "f"(lo));
    return u;
}
__device__ __forceinline__ uint32_t addh2(uint32_t a, uint32_t b) {
    uint32_t r;
    asm("add.f16x2 %0, %1, %2;" : "=r"(r) : "r"(a), "r"(b));
    return r;
}
// silu on an f16x2 pair via ONE MUFU: silu(x) = (x/2)*(1+tanh(x/2))
__device__ __forceinline__ uint32_t silu16(uint32_t x) {
    uint32_t hx, t, o, r;
    asm("mul.f16x2 %0, %1, %2;" : "=r"(hx) : "r"(x), "r"(0x38003800u));   // x/2
    asm("tanh.approx.f16x2 %0, %1;" : "=r"(t) : "r"(hx));
    asm("add.f16x2 %0, %1, %2;" : "=r"(o) : "r"(t), "r"(0x3C003C00u));    // 1+t
    asm("mul.f16x2 %0, %1, %2;" : "=r"(r) : "r"(hx), "r"(o));
    return r;
}
__device__ __forceinline__ uint32_t smem_u32(const void* p) {
    uint32_t a;
    asm("{ .reg .u64 t; cvta.to.shared.u64 t, %1; cvt.u32.u64 %0, t; }" : "=r"(a) : "l"(p));
    return a;
}
__device__ __forceinline__ void cpa16(uint32_t saddr, const void* g) {
    asm volatile("cp.async.cg.shared.global [%0], [%1], 16;\n" ::"r"(saddr), "l"(g));
}
__device__ __forceinline__ void cpcommit() { asm volatile("cp.async.commit_group;\n"); }
template <int N>
__device__ __forceinline__ void cpwait() { asm volatile("cp.async.wait_group %0;\n" ::"n"(N)); }

// fp16 mma m16n8k16, fp16 accumulate
__device__ __forceinline__ void mma16h(uint32_t d[2], const uint32_t a[4],
                                       const uint32_t b0, const uint32_t b1) {
    asm volatile(
        "mma.sync.aligned.m16n8k16.row.col.f16.f16.f16.f16 "
        "{%0,%1}, {%2,%3,%4,%5}, {%6,%7}, {%0,%1};\n"
        : "+r"(d[0]), "+r"(d[1])
        : "r"(a[0]), "r"(a[1]), "r"(a[2]), "r"(a[3]), "r"(b0), "r"(b1));
}
// fp16 mma m16n8k16, fp32 accumulate (fused GEMM3)
__device__ __forceinline__ void mma16(float d[4], const uint32_t a[4],
                                      const uint32_t b[2], const float c[4]) {
    asm volatile(
        "mma.sync.aligned.m16n8k16.row.col.f32.f16.f16.f32 "
        "{%0,%1,%2,%3}, {%4,%5,%6,%7}, {%8,%9}, {%10,%11,%12,%13};\n"
        : "=f"(d[0]), "=f"(d[1]), "=f"(d[2]), "=f"(d[3])
        : "r"(a[0]), "r"(a[1]), "r"(a[2]), "r"(a[3]),
          "r"(b[0]), "r"(b[1]),
          "f"(c[0]), "f"(c[1]), "f"(c[2]), "f"(c[3]));
}
// tf32 mma m16n8k8 (dyn phases)
__device__ __forceinline__ void mma8(float d[4], const uint32_t a[4],
                                     const uint32_t b[2], const float c[4]) {
    asm volatile(
        "mma.sync.aligned.m16n8k8.row.col.f32.tf32.tf32.f32 "
        "{%0,%1,%2,%3}, {%4,%5,%6,%7}, {%8,%9}, {%10,%11,%12,%13};\n"
        : "=f"(d[0]), "=f"(d[1]), "=f"(d[2]), "=f"(d[3])
        : "r"(a[0]), "r"(a[1]), "r"(a[2]), "r"(a[3]),
          "r"(b[0]), "r"(b[1]),
          "f"(c[0]), "f"(c[1]), "f"(c[2]), "f"(c[3]));
}

// ============================================================================
// Kernel 0: build PAIRED fragment images (unchanged).
// ============================================================================
__global__ void prep_kernel(const float* __restrict__ W1, const float* __restrict__ W2,
                            const float* __restrict__ W3, const float* __restrict__ U) {
    __half* gh = (__half*)g_wfrag;
    int idx = blockIdx.x * 256 + threadIdx.x;
    if (idx < 65536) {                    // W2 [256k x 256n]
        int k = idx >> 8, n = idx & 255;
        int chunk = k >> 5, ks = (k >> 4) & 1, kl = k & 15;
        int b_idx = kl >> 3, q = (kl & 7) >> 1, par = kl & 1;
        int wn = n >> 5, nt = (n >> 3) & 3, g = n & 7;
        int ntp = nt >> 1, sub = nt & 1;
        int slot4 = chunk * 1024 + ((ks * 8 + wn) * 2 + ntp) * 32 + g * 4 + q;
        gh[slot4 * 8 + sub * 4 + b_idx * 2 + par] = __float2half_rn(W2[idx]);
    } else if (idx < 69632) {             // W1 [16k x 256n]
        int t = idx - 65536;
        int k = t >> 8, n = t & 255;
        int b_idx = k >> 3, q = (k & 7) >> 1, par = k & 1;
        int wn = n >> 5, nt = (n >> 3) & 3, g = n & 7;
        int ntp = nt >> 1, sub = nt & 1;
        int slot4 = (wn * 2 + ntp) * 32 + g * 4 + q;
        gh[65536 + slot4 * 8 + sub * 4 + b_idx * 2 + par] = __float2half_rn(W1[t]);
    } else if (idx < 73728) {             // W3 [256k x 16n]
        int t = idx - 69632;
        int k = t >> 4, n = t & 15;
        int ks = k >> 4, kl = k & 15;
        int b_idx = kl >> 3, q = (kl & 7) >> 1, par = kl & 1;
        int nt = n >> 3, g = n & 7;
        int slot = (ks * 2 + nt) * 32 + g * 4 + q;
        gh[69632 + slot * 4 + b_idx * 2 + par] = __float2half_rn(W3[t]);
    } else if (idx < 74752) {             // ufA: kk-paired tf32 frags (z@U)
        int t = idx - 73728;
        int lane = t & 31, nt = (t >> 5) & 1, kk = t >> 6;
        int g = lane >> 2, q = lane & 3;
        int b4 = ((kk >> 1) * 2 + nt) * 32 + lane;
        g_ufA[b4 * 4 + (kk & 1) * 2]     = nan0(U[(kk * 8 + q) * RR + nt * 8 + g]);
        g_ufA[b4 * 4 + (kk & 1) * 2 + 1] = nan0(U[(kk * 8 + q + 4) * RR + nt * 8 + g]);
    } else if (idx < 75776) {             // ufB: nt-paired tf32 frags (cs@Ut)
        int t = idx - 74752;
        int lane = t & 31, ntt = (t >> 5) & 15, ks = t >> 9;
        int g = lane >> 2, q = lane & 3;
        int wnb = ntt >> 2, ntl = ntt & 3, ntp = ntl >> 1, sub = ntl & 1;
        int b4 = (ks * 8 + wnb * 2 + ntp) * 32 + lane;
        g_ufB[b4 * 4 + sub * 2]     = nan0(U[(ntt * 8 + g) * RR + ks * 8 + q]);
        g_ufB[b4 * 4 + sub * 2 + 1] = nan0(U[(ntt * 8 + g) * RR + ks * 8 + q + 4]);
    }
}

// ============================================================================
// Fused kernel: 128 rows/CTA, 1024 threads, 1 CTA/SM, W2 fully resident.
// ============================================================================
__global__ void __launch_bounds__(1024, 1) fused_kernel(
    const float* __restrict__ pt, const float* __restrict__ z,
    const float* __restrict__ dt_norm_g, const float* __restrict__ U,
    const float* __restrict__ b1, const float* __restrict__ b2,
    const float* __restrict__ b3, float* __restrict__ out) {
    extern __shared__ char smc[];
    __shared__ uint32_t b1p[128], b2p[128];   // packed f16x2 bias pairs
    __shared__ float b3s[16], cn2s[16];

    const int tid = threadIdx.x;
    const int wid = tid >> 5, lane = tid & 31;
    const int g = lane >> 2, q = lane & 3;
    const int r0 = blockIdx.x * MTILE;
    const uint32_t sb = smem_u32(smc);
    const char* gw = (const char*)g_wfrag;

    // group 0: W1 frags + W3 frags (1024 threads x 16B = 16KB)
    if (tid < 512) {
        cpa16(sb + OFF_W1F + tid * 16, gw + 131072 + tid * 16);
    } else {
        int t = tid - 512;
        cpa16(sb + OFF_W3F + t * 16, gw + 139264 + t * 16);
    }
    cpcommit();
    // groups 1..8: all 8 W2 chunks (deep pipeline, one cpa16/thread/chunk)
#pragma unroll
    for (int c = 0; c < 8; c++) {
        cpa16(sb + OFF_W2F + c * 16384 + tid * 16, gw + (size_t)c * 16384 + tid * 16);
        cpcommit();
    }

    // --- stage x as fp16 A-frags (nan0): 2048 elements ---
    __half* xf = (__half*)(smc + OFF_XF);
#pragma unroll
    for (int i = 0; i < 2; i++) {
        int idx = tid + i * 1024;
        int r = idx >> 4, c = idx & 15;
        float v = nan0(pt[(size_t)(r0 + r) * GD + c]);
        int rr = r & 15, rb = r >> 4;
        int gg = rr & 7, hi8 = rr >> 3;
        int qq = (c & 7) >> 1, par = c & 1;
        int a_idx = ((c >= 8) ? 2 : 0) + hi8;
        int ln = gg * 4 + qq;
        xf[(rb * 32 + ln) * 8 + a_idx * 2 + par] = __float2half_rn(v);
    }
    if (tid < 128) {
        b1p[tid] = packh(b1[2 * tid], b1[2 * tid + 1]);
        b2p[tid] = packh(b2[2 * tid], b2[2 * tid + 1]);
    }
    if (tid < 16) {
        b3s[tid] = b3[tid];
        float s = 0.f;
        for (int j = 0; j < ZD; j++) {
            float u = nan0(U[j * RR + tid]);
            s += u * u;
        }
        cn2s[tid] = s;
    }
    cpwait<8>();     // W1/W3 landed; 8 W2 chunks in flight
    __syncthreads();

    const int wm = wid >> 3, wn = wid & 7;   // 4 x 8 warps (GEMM1/2)

    // ================= GEMM1: h1 = silu(x @ W1 + b1) -> h1 A-frags =========
#pragma unroll
    for (int mt = 0; mt < 2; mt++) {
        int rb = wm * 2 + mt;                       // 0..7
        uint4 Av = *(const uint4*)(smc + OFF_XF + (rb * 32 + lane) * 16);
        uint32_t A[4] = {Av.x, Av.y, Av.z, Av.w};
#pragma unroll
        for (int ntp = 0; ntp < 2; ntp++) {
            uint4 Bp = *(const uint4*)(smc + OFF_W1F + ((wn * 2 + ntp) * 32 + lane) * 16);
            uint32_t d0[2] = {0u, 0u}, d1[2] = {0u, 0u};
            mma16h(d0, A, Bp.x, Bp.y);
            mma16h(d1, A, Bp.z, Bp.w);
            uint32_t bias0 = b1p[(wn * 4 + 2 * ntp) * 4 + q];
            uint32_t bias1 = b1p[(wn * 4 + 2 * ntp + 1) * 4 + q];
            int kk = wn * 2 + ntp;
            uint4 pk;
            pk.x = silu16(addh2(d0[0], bias0));
            pk.y = silu16(addh2(d0[1], bias0));
            pk.z = silu16(addh2(d1[0], bias1));
            pk.w = silu16(addh2(d1[1], bias1));
            *(uint4*)(smc + OFF_H1F + ((rb * 16 + kk) * 32 + lane) * 16) = pk;
        }
    }
    __syncthreads();

    // ================= GEMM2: resident W2, per-chunk wait mostly free ======
    uint32_t acc[2][4][2];
#pragma unroll
    for (int mt = 0; mt < 2; mt++)
#pragma unroll
        for (int nt = 0; nt < 4; nt++) {
            acc[mt][nt][0] = 0u;
            acc[mt][nt][1] = 0u;
        }

#pragma unroll
    for (int c = 0; c < 8; c++) {
        if (c == 0) cpwait<7>(); else if (c == 1) cpwait<6>();
        else if (c == 2) cpwait<5>(); else if (c == 3) cpwait<4>();
        else if (c == 4) cpwait<3>(); else if (c == 5) cpwait<2>();
        else if (c == 6) cpwait<1>(); else cpwait<0>();
        __syncthreads();      // cross-thread visibility of chunk c
        const char* wb = smc + OFF_W2F + c * 16384;
        uint4 Ar[2][2];
#pragma unroll
        for (int ks = 0; ks < 2; ks++)
#pragma unroll
            for (int mt = 0; mt < 2; mt++)
                Ar[ks][mt] = *(const uint4*)(smc + OFF_H1F +
                                (((wm * 2 + mt) * 16 + c * 2 + ks) * 32 + lane) * 16);
#pragma unroll
        for (int ks = 0; ks < 2; ks++) {
            uint32_t A0[4] = {Ar[ks][0].x, Ar[ks][0].y, Ar[ks][0].z, Ar[ks][0].w};
            uint32_t A1[4] = {Ar[ks][1].x, Ar[ks][1].y, Ar[ks][1].z, Ar[ks][1].w};
#pragma unroll
            for (int ntp = 0; ntp < 2; ntp++) {
                uint4 Bp = *(const uint4*)(wb + (((ks * 8 + wn) * 2 + ntp) * 32 + lane) * 16);
                mma16h(acc[0][2 * ntp],     A0, Bp.x, Bp.y);
                mma16h(acc[1][2 * ntp],     A1, Bp.x, Bp.y);
                mma16h(acc[0][2 * ntp + 1], A0, Bp.z, Bp.w);
                mma16h(acc[1][2 * ntp + 1], A1, Bp.z, Bp.w);
            }
        }
    }
    __syncthreads();   // W2F + h1 frags fully consumed

    // --- issue z (-> dead W2F) and ufA (-> dead XF+W1F) loads ---
    {
        float* zs = (float*)(smc + OFF_ZS);
#pragma unroll
        for (int i = 0; i < 4; i++) {
            int idx = tid + i * 1024;               // 4096 x float4
            int row = idx >> 5, c4 = (idx & 31) << 2;
            cpa16(smem_u32(&zs[row * 132 + c4]), &z[(size_t)(r0 + row) * ZD + c4]);
        }
        if (tid < 512) cpa16(sb + OFF_UFA + tid * 16, (const char*)g_ufA + tid * 16);
        cpcommit();
    }

    // ===== fused epilogue: silu(acc+b2) -> in-register GEMM3 partials ======
    float* hp = (float*)(smc + OFF_HP);   // [8 wn][16 col][128 row], XOR-swizzled
    {
        float hpacc[2][2][4];
#pragma unroll
        for (int mt = 0; mt < 2; mt++)
#pragma unroll
            for (int n3 = 0; n3 < 2; n3++)
#pragma unroll
                for (int i = 0; i < 4; i++) hpacc[mt][n3][i] = 0.f;
#pragma unroll
        for (int mt = 0; mt < 2; mt++) {
#pragma unroll
            for (int ntp = 0; ntp < 2; ntp++) {
                uint32_t bias0 = b2p[(wn * 4 + 2 * ntp) * 4 + q];
                uint32_t bias1 = b2p[(wn * 4 + 2 * ntp + 1) * 4 + q];
                uint32_t A[4] = {silu16(addh2(acc[mt][2 * ntp][0], bias0)),
                                 silu16(addh2(acc[mt][2 * ntp][1], bias0)),
                                 silu16(addh2(acc[mt][2 * ntp + 1][0], bias1)),
                                 silu16(addh2(acc[mt][2 * ntp + 1][1], bias1))};
                int kk = wn * 2 + ntp;
#pragma unroll
                for (int n3 = 0; n3 < 2; n3++) {
                    uint2 Bv = *(const uint2*)(smc + OFF_W3F + ((kk * 2 + n3) * 32 + lane) * 8);
                    uint32_t B[2] = {Bv.x, Bv.y};
                    mma16(hpacc[mt][n3], A, B, hpacc[mt][n3]);
                }
            }
        }
        float* hpw = hp + wn * 2048;
#pragma unroll
        for (int mt = 0; mt < 2; mt++) {
            int rb = wm * 32 + mt * 16;
#pragma unroll
            for (int n3 = 0; n3 < 2; n3++) {
                int c0 = n3 * 8 + 2 * q, c1 = c0 + 1;
                hpw[c0 * 128 + ((rb + g) ^ ((c0 & 3) << 3))]     = hpacc[mt][n3][0];
                hpw[c1 * 128 + ((rb + g) ^ ((c1 & 3) << 3))]     = hpacc[mt][n3][1];
                hpw[c0 * 128 + ((rb + g + 8) ^ ((c0 & 3) << 3))] = hpacc[mt][n3][2];
                hpw[c1 * 128 + ((rb + g + 8) ^ ((c1 & 3) << 3))] = hpacc[mt][n3][3];
            }
        }
    }
    __syncthreads();   // hp published; W3F reads done

    // --- issue ufB (-> dead W3F region) ---
    if (tid < 512) cpa16(sb + OFF_UFB + tid * 16, (const char*)g_ufB + tid * 16);
    cpcommit();

    // ================= per-row epilogue: lamg, d -> smem =================
    float* ds = (float*)(smc + OFF_DS);
    float* lg = (float*)(smc + OFF_LG);
    if (tid < 128) {
        int row = tid;
        float s[16], fro2 = 0.f;
#pragma unroll
        for (int r = 0; r < 16; r++) {
            float v = b3s[r];
#pragma unroll
            for (int p = 0; p < 8; p++)
                v += hp[p * 2048 + r * 128 + (row ^ ((r & 3) << 3))];
            float sr = 2.f / (1.f + __expf(-v));
            s[r] = sr;
            fro2 += sr * sr * cn2s[r];
        }
        float fro = sqrtf(fro2);
        float scale = fminf(2.2627416997969522f / fmaxf(fro, 1e-9f), 1.f);

        float v = dt_norm_g[r0 + row];
        if (isnan(v)) v = 0.f;
        v = fminf(fmaxf(v, 0.f), 1.f);
        float logdt = fminf(-3.f + v * 11.f, 2.7781512503836436f);   // log10(600)
        float dt = fmaxf(expf(logdt * 2.302585092994046f), 1e-30f);
        float lamg = expf(-0.1f * dt);
        lg[row] = lamg;
#pragma unroll
        for (int r = 0; r < 16; r++) {
            float ss = s[r] * scale;
            float lp = expf(-ss * ss * dt) * lamg;
            ds[row * 20 + r] = lp - lamg;
        }
    }
    cpwait<1>();       // z + ufA landed (ufB may still fly)
    __syncthreads();

    const float* zs = (const float*)(smc + OFF_ZS);
    float* cs = (float*)(smc + OFF_CS);
    const char* ufA = smc + OFF_UFA;
    const char* ufB = smc + OFF_UFB;

    // ===== GEMM A: cs[row][r] = d[row][r] * (z @ U)[row][r]  (16 warps) ====
    if (wid < 16) {
        int mt = wid >> 1, nt = wid & 1;            // mt 0..7 -> 128 rows
        int rbase = mt * 16, cbase = nt * 8;
        float accA[4] = {0.f, 0.f, 0.f, 0.f};
#pragma unroll
        for (int kp = 0; kp < 8; kp++) {
            uint4 Bv = *(const uint4*)(ufA + ((kp * 2 + nt) * 32 + lane) * 16);
#pragma unroll
            for (int sub = 0; sub < 2; sub++) {
                int k0 = (kp * 2 + sub) * 8;
                uint32_t a[4] = {
                    fbits(zs[(rbase + g) * 132 + k0 + q]),
                    fbits(zs[(rbase + g + 8) * 132 + k0 + q]),
                    fbits(zs[(rbase + g) * 132 + k0 + q + 4]),
                    fbits(zs[(rbase + g + 8) * 132 + k0 + q + 4])};
                uint32_t b[2] = {sub ? Bv.z : Bv.x, sub ? Bv.w : Bv.y};
                mma8(accA, a, b, accA);
            }
        }
        int row0 = rbase + g, row1 = rbase + g + 8;
        int c0 = cbase + 2 * q, c1 = c0 + 1;
        cs[row0 * 20 + c0] = accA[0] * ds[row0 * 20 + c0];
        cs[row0 * 20 + c1] = accA[1] * ds[row0 * 20 + c1];
        cs[row1 * 20 + c0] = accA[2] * ds[row1 * 20 + c0];
        cs[row1 * 20 + c1] = accA[3] * ds[row1 * 20 + c1];
    }
    cpwait<0>();       // ufB landed
    __syncthreads();

    // ===== GEMM B + identity, direct to global (32 warps) =====
    {
        int mt = wid & 7, wnb = wid >> 3;           // mt 0..7, wnb 0..3
        int rbase = mt * 16;
        float accB[4][4];
#pragma unroll
        for (int nt = 0; nt < 4; nt++)
#pragma unroll
            for (int i = 0; i < 4; i++) accB[nt][i] = 0.f;
#pragma unroll
        for (int ks = 0; ks < 2; ks++) {
            int k0 = ks * 8;
            uint32_t a[4] = {
                fbits(cs[(rbase + g) * 20 + k0 + q]),
                fbits(cs[(rbase + g + 8) * 20 + k0 + q]),
                fbits(cs[(rbase + g) * 20 + k0 + q + 4]),
                fbits(cs[(rbase + g + 8) * 20 + k0 + q + 4])};
#pragma unroll
            for (int ntp = 0; ntp < 2; ntp++) {
                uint4 Bp = *(const uint4*)(ufB + ((ks * 8 + wnb * 2 + ntp) * 32 + lane) * 16);
                uint32_t B0[2] = {Bp.x, Bp.y}, B1[2] = {Bp.z, Bp.w};
                mma8(accB[2 * ntp],     a, B0, accB[2 * ntp]);
                mma8(accB[2 * ntp + 1], a, B1, accB[2 * ntp + 1]);
            }
        }
        int row0 = rbase + g, row1 = rbase + g + 8;
        float l0 = lg[row0], l1 = lg[row1];
        size_t gr0 = (size_t)(r0 + row0) * ZD, gr1 = (size_t)(r0 + row1) * ZD;
#pragma unroll
        for (int nt = 0; nt < 4; nt++) {
            int cb = (wnb * 4 + nt) * 8;
            int c0 = cb + 2 * q;
            float2 z0 = *(const float2*)&zs[row0 * 132 + c0];
            float2 o0;
            o0.x = l0 * z0.x + accB[nt][0];
            o0.y = l0 * z0.y + accB[nt][1];
            *(float2*)&out[gr0 + c0] = o0;
            float2 z1 = *(const float2*)&zs[row1 * 132 + c0];
            float2 o1;
            o1.x = l1 * z1.x + accB[nt][2];
            o1.y = l1 * z1.y + accB[nt][3];
            *(float2*)&out[gr1 + c0] = o1;
        }
    }
}

extern "C" void kernel_launch(void* const* d_in, const int* in_sizes, int n_in,
                              void* d_out, int out_size) {
    const float* pt      = (const float*)d_in[0];
    const float* z       = (const float*)d_in[1];
    const float* dt_norm = (const float*)d_in[2];
    const float* base_U  = (const float*)d_in[3];
    const float* W1      = (const float*)d_in[4];
    const float* b1      = (const float*)d_in[5];
    const float* W2      = (const float*)d_in[6];
    const float* b2      = (const float*)d_in[7];
    const float* W3      = (const float*)d_in[8];
    const float* b3      = (const float*)d_in[9];
    float* out = (float*)d_out;

    cudaFuncSetAttribute(fused_kernel, cudaFuncAttributeMaxDynamicSharedMemorySize, SMEM_BYTES);

    prep_kernel<<<296, 256>>>(W1, W2, W3, base_U);
    fused_kernel<<<NBLK, 1024, SMEM_BYTES>>>(pt, z, dt_norm, base_U, b1, b2, b3, out);
}

// round 15
// speedup vs baseline: 1.1096x; 1.1096x over previous
#include <cuda_runtime.h>
#include <cuda_fp16.h>
#include <cstdint>
#include <math.h>

#define BATCH 262144
#define GD 16
#define HID 256
#define RR 16
#define ZD 128
#define MTILE 64
#define NBLK (BATCH / MTILE)

// ---- fused kernel dynamic smem layout (bytes) ----
#define OFF_XF   0        // x A-frags 2048
#define OFF_W1F  2048     // W1 B-frags 8192
#define OFF_H1F  10240    // h1/h2 A-frags 32768
#define OFF_RING 43008    // W2 ring 4x16384 = 65536 (2 pair-buffers)
#define SMEM_BYTES 108544
// post-GEMM2 overlays
#define OFF_UFA  0             // 8192 (over XF+W1F)
#define OFF_ZS   43008         // 64*132*4 = 33792 (over ring)
#define OFF_W3F  76800         // 8192 (over ring)
#define OFF_HP   84992         // 2*64*20*4 = 10240 (over ring)
#define OFF_CS   84992         // 5120 (over hp lower, after hp reads)
#define OFF_DS   90112         // 5120 (over hp upper, after hp reads)
#define OFF_LG   95232         // 256
#define OFF_UFB  95488         // 8192

// device-global weight images (allocation-free scratch)
__device__ __align__(256) uint32_t g_wfrag[36864];  // W2 8x16KB, W1 @byte 131072, W3 @byte 139264
__device__ __align__(256) float g_ufA[2048];
__device__ __align__(256) float g_ufB[2048];

__device__ __forceinline__ uint32_t fbits(float x) { return __float_as_uint(x); }
__device__ __forceinline__ float nan0(float v) { return isfinite(v) ? v : 0.f; }
__device__ __forceinline__ uint32_t packh(float lo, float hi) {
    uint32_t u;
    asm("cvt.rn.f16x2.f32 %0, %1, %2;" : "=r"(u) : "f"(hi), "f"(lo));
    return u;
}
__device__ __forceinline__ uint32_t addh2(uint32_t a, uint32_t b) {
    uint32_t r;
    asm("add.f16x2 %0, %1, %2;" : "=r"(r) : "r"(a), "r"(b));
    return r;
}
// silu on an f16x2 pair via ONE MUFU: silu(x) = (x/2)*(1+tanh(x/2))
__device__ __forceinline__ uint32_t silu16(uint32_t x) {
    uint32_t hx, t, o, r;
    asm("mul.f16x2 %0, %1, %2;" : "=r"(hx) : "r"(x), "r"(0x38003800u));   // x/2
    asm("tanh.approx.f16x2 %0, %1;" : "=r"(t) : "r"(hx));
    asm("add.f16x2 %0, %1, %2;" : "=r"(o) : "r"(t), "r"(0x3C003C00u));    // 1+t
    asm("mul.f16x2 %0, %1, %2;" : "=r"(r) : "r"(hx), "r"(o));
    return r;
}
__device__ __forceinline__ uint32_t smem_u32(const void* p) {
    uint32_t a;
    asm("{ .reg .u64 t; cvta.to.shared.u64 t, %1; cvt.u32.u64 %0, t; }" : "=r"(a) : "l"(p));
    return a;
}
__device__ __forceinline__ void cpa16(uint32_t saddr, const void* g) {
    asm volatile("cp.async.cg.shared.global [%0], [%1], 16;\n" ::"r"(saddr), "l"(g));
}
__device__ __forceinline__ void cpcommit() { asm volatile("cp.async.commit_group;\n"); }
template <int N>
__device__ __forceinline__ void cpwait() { asm volatile("cp.async.wait_group %0;\n" ::"n"(N)); }

// fp16 mma m16n8k16, fp16 accumulate
__device__ __forceinline__ void mma16h(uint32_t d[2], const uint32_t a[4],
                                       const uint32_t b0, const uint32_t b1) {
    asm volatile(
        "mma.sync.aligned.m16n8k16.row.col.f16.f16.f16.f16 "
        "{%0,%1}, {%2,%3,%4,%5}, {%6,%7}, {%0,%1};\n"
        : "+r"(d[0]), "+r"(d[1])
        : "r"(a[0]), "r"(a[1]), "r"(a[2]), "r"(a[3]), "r"(b0), "r"(b1));
}
// fp16 mma m16n8k16, fp32 accumulate (GEMM3)
__device__ __forceinline__ void mma16(float d[4], const uint32_t a[4],
                                      const uint32_t b[2], const float c[4]) {
    asm volatile(
        "mma.sync.aligned.m16n8k16.row.col.f32.f16.f16.f32 "
        "{%0,%1,%2,%3}, {%4,%5,%6,%7}, {%8,%9}, {%10,%11,%12,%13};\n"
        : "=f"(d[0]), "=f"(d[1]), "=f"(d[2]), "=f"(d[3])
        : "r"(a[0]), "r"(a[1]), "r"(a[2]), "r"(a[3]),
          "r"(b[0]), "r"(b[1]),
          "f"(c[0]), "f"(c[1]), "f"(c[2]), "f"(c[3]));
}
// tf32 mma m16n8k8 (dyn phases)
__device__ __forceinline__ void mma8(float d[4], const uint32_t a[4],
                                     const uint32_t b[2], const float c[4]) {
    asm volatile(
        "mma.sync.aligned.m16n8k8.row.col.f32.tf32.tf32.f32 "
        "{%0,%1,%2,%3}, {%4,%5,%6,%7}, {%8,%9}, {%10,%11,%12,%13};\n"
        : "=f"(d[0]), "=f"(d[1]), "=f"(d[2]), "=f"(d[3])
        : "r"(a[0]), "r"(a[1]), "r"(a[2]), "r"(a[3]),
          "r"(b[0]), "r"(b[1]),
          "f"(c[0]), "f"(c[1]), "f"(c[2]), "f"(c[3]));
}

// ============================================================================
// Kernel 0: build PAIRED fragment images (unchanged).
// ============================================================================
__global__ void prep_kernel(const float* __restrict__ W1, const float* __restrict__ W2,
                            const float* __restrict__ W3, const float* __restrict__ U) {
    __half* gh = (__half*)g_wfrag;
    int idx = blockIdx.x * 256 + threadIdx.x;
    if (idx < 65536) {                    // W2 [256k x 256n]
        int k = idx >> 8, n = idx & 255;
        int chunk = k >> 5, ks = (k >> 4) & 1, kl = k & 15;
        int b_idx = kl >> 3, q = (kl & 7) >> 1, par = kl & 1;
        int wn = n >> 5, nt = (n >> 3) & 3, g = n & 7;
        int ntp = nt >> 1, sub = nt & 1;
        int slot4 = chunk * 1024 + ((ks * 8 + wn) * 2 + ntp) * 32 + g * 4 + q;
        gh[slot4 * 8 + sub * 4 + b_idx * 2 + par] = __float2half_rn(W2[idx]);
    } else if (idx < 69632) {             // W1 [16k x 256n]
        int t = idx - 65536;
        int k = t >> 8, n = t & 255;
        int b_idx = k >> 3, q = (k & 7) >> 1, par = k & 1;
        int wn = n >> 5, nt = (n >> 3) & 3, g = n & 7;
        int ntp = nt >> 1, sub = nt & 1;
        int slot4 = (wn * 2 + ntp) * 32 + g * 4 + q;
        gh[65536 + slot4 * 8 + sub * 4 + b_idx * 2 + par] = __float2half_rn(W1[t]);
    } else if (idx < 73728) {             // W3 [256k x 16n]
        int t = idx - 69632;
        int k = t >> 4, n = t & 15;
        int ks = k >> 4, kl = k & 15;
        int b_idx = kl >> 3, q = (kl & 7) >> 1, par = kl & 1;
        int nt = n >> 3, g = n & 7;
        int slot = (ks * 2 + nt) * 32 + g * 4 + q;
        gh[69632 + slot * 4 + b_idx * 2 + par] = __float2half_rn(W3[t]);
    } else if (idx < 74752) {             // ufA: kk-paired tf32 frags (z@U)
        int t = idx - 73728;
        int lane = t & 31, nt = (t >> 5) & 1, kk = t >> 6;
        int g = lane >> 2, q = lane & 3;
        int b4 = ((kk >> 1) * 2 + nt) * 32 + lane;
        g_ufA[b4 * 4 + (kk & 1) * 2]     = nan0(U[(kk * 8 + q) * RR + nt * 8 + g]);
        g_ufA[b4 * 4 + (kk & 1) * 2 + 1] = nan0(U[(kk * 8 + q + 4) * RR + nt * 8 + g]);
    } else if (idx < 75776) {             // ufB: nt-paired tf32 frags (cs@Ut)
        int t = idx - 74752;
        int lane = t & 31, ntt = (t >> 5) & 15, ks = t >> 9;
        int g = lane >> 2, q = lane & 3;
        int wnb = ntt >> 2, ntl = ntt & 3, ntp = ntl >> 1, sub = ntl & 1;
        int b4 = (ks * 8 + wnb * 2 + ntp) * 32 + lane;
        g_ufB[b4 * 4 + sub * 2]     = nan0(U[(ntt * 8 + g) * RR + ks * 8 + q]);
        g_ufB[b4 * 4 + sub * 2 + 1] = nan0(U[(ntt * 8 + g) * RR + ks * 8 + q + 4]);
    }
}

// ============================================================================
// Fused kernel: 64 rows/CTA, 512 threads, 2 CTAs/SM.
// GEMM2 pair-processing: 4-slot ring, 4 barriers, one pair always in flight.
// ============================================================================
__global__ void __launch_bounds__(512, 2) fused_kernel(
    const float* __restrict__ pt, const float* __restrict__ z,
    const float* __restrict__ dt_norm_g, const float* __restrict__ U,
    const float* __restrict__ b1, const float* __restrict__ b2,
    const float* __restrict__ b3, float* __restrict__ out) {
    extern __shared__ char smc[];
    __shared__ uint32_t b1p[128], b2p[128];   // packed f16x2 bias pairs
    __shared__ float b3s[16], cn2s[16];

    const int tid = threadIdx.x;
    const int wid = tid >> 5, lane = tid & 31;
    const int g = lane >> 2, q = lane & 3;
    const int r0 = blockIdx.x * MTILE;
    const uint32_t sb = smem_u32(smc);
    const char* gw = (const char*)g_wfrag;

    // G0: W1 frags (8KB)
    if (tid < 512) cpa16(sb + OFF_W1F + tid * 16, gw + 131072 + tid * 16);
    cpcommit();
    // G1: W2 pair 0 (chunks 0,1 -> ring buffer 0, 32KB)
#pragma unroll
    for (int i = 0; i < 4; i++) {
        int idx = tid + i * 512;
        cpa16(sb + OFF_RING + idx * 16, gw + idx * 16);
    }
    cpcommit();

    // --- stage x as fp16 A-frags (nan0) ---
    __half* xf = (__half*)(smc + OFF_XF);
#pragma unroll
    for (int i = 0; i < 2; i++) {
        int idx = tid + i * 512;
        int r = idx >> 4, c = idx & 15;
        float v = nan0(pt[(size_t)(r0 + r) * GD + c]);
        int rr = r & 15, rb = r >> 4;
        int gg = rr & 7, hi8 = rr >> 3;
        int qq = (c & 7) >> 1, par = c & 1;
        int a_idx = ((c >= 8) ? 2 : 0) + hi8;
        int ln = gg * 4 + qq;
        xf[(rb * 32 + ln) * 8 + a_idx * 2 + par] = __float2half_rn(v);
    }
    if (tid < 128) {
        b1p[tid] = packh(b1[2 * tid], b1[2 * tid + 1]);
        b2p[tid] = packh(b2[2 * tid], b2[2 * tid + 1]);
    }
    if (tid < 16) {
        b3s[tid] = b3[tid];
        float s = 0.f;
        for (int j = 0; j < ZD; j++) {
            float u = nan0(U[j * RR + tid]);
            s += u * u;
        }
        cn2s[tid] = s;
    }
    cpwait<1>();     // W1 landed; pair 0 in flight
    __syncthreads();

    const int wm = wid >> 3, wn = wid & 7;   // 2 x 8 warps (GEMM1/2)

    // ================= GEMM1: h1 = silu(x @ W1 + b1) -> h1 A-frags =========
#pragma unroll
    for (int mt = 0; mt < 2; mt++) {
        int rb = wm * 2 + mt;
        uint4 Av = *(const uint4*)(smc + OFF_XF + (rb * 32 + lane) * 16);
        uint32_t A[4] = {Av.x, Av.y, Av.z, Av.w};
#pragma unroll
        for (int ntp = 0; ntp < 2; ntp++) {
            uint4 Bp = *(const uint4*)(smc + OFF_W1F + ((wn * 2 + ntp) * 32 + lane) * 16);
            uint32_t d0[2] = {0u, 0u}, d1[2] = {0u, 0u};
            mma16h(d0, A, Bp.x, Bp.y);
            mma16h(d1, A, Bp.z, Bp.w);
            uint32_t bias0 = b1p[(wn * 4 + 2 * ntp) * 4 + q];
            uint32_t bias1 = b1p[(wn * 4 + 2 * ntp + 1) * 4 + q];
            int kk = wn * 2 + ntp;
            uint4 pk;
            pk.x = silu16(addh2(d0[0], bias0));
            pk.y = silu16(addh2(d0[1], bias0));
            pk.z = silu16(addh2(d1[0], bias1));
            pk.w = silu16(addh2(d1[1], bias1));
            *(uint4*)(smc + OFF_H1F + ((rb * 16 + kk) * 32 + lane) * 16) = pk;
        }
    }
    __syncthreads();

    // ===== GEMM2: 4 pair-iterations, one pair in flight, 4 barriers ========
    uint32_t acc[2][4][2];
#pragma unroll
    for (int mt = 0; mt < 2; mt++)
#pragma unroll
        for (int nt = 0; nt < 4; nt++) {
            acc[mt][nt][0] = 0u;
            acc[mt][nt][1] = 0u;
        }

#pragma unroll
    for (int j = 0; j < 4; j++) {
        cpwait<0>();        // pair j landed
        __syncthreads();    // pair j visible; buffer (j+1)&1 free
        if (j < 3) {        // prefetch pair j+1 into the other buffer
#pragma unroll
            for (int i = 0; i < 4; i++) {
                int idx = tid + i * 512;
                cpa16(sb + OFF_RING + ((j + 1) & 1) * 32768 + idx * 16,
                      gw + (size_t)(j + 1) * 32768 + idx * 16);
            }
            cpcommit();
        }
        const char* wbb = smc + OFF_RING + (j & 1) * 32768;
#pragma unroll
        for (int cc = 0; cc < 2; cc++) {
            int c = 2 * j + cc;
            const char* wb = wbb + cc * 16384;
            uint4 Ar[2][2];
#pragma unroll
            for (int ks = 0; ks < 2; ks++)
#pragma unroll
                for (int mt = 0; mt < 2; mt++)
                    Ar[ks][mt] = *(const uint4*)(smc + OFF_H1F +
                                    (((wm * 2 + mt) * 16 + c * 2 + ks) * 32 + lane) * 16);
#pragma unroll
            for (int ks = 0; ks < 2; ks++) {
                uint32_t A0[4] = {Ar[ks][0].x, Ar[ks][0].y, Ar[ks][0].z, Ar[ks][0].w};
                uint32_t A1[4] = {Ar[ks][1].x, Ar[ks][1].y, Ar[ks][1].z, Ar[ks][1].w};
#pragma unroll
                for (int ntp = 0; ntp < 2; ntp++) {
                    uint4 Bp = *(const uint4*)(wb + (((ks * 8 + wn) * 2 + ntp) * 32 + lane) * 16);
                    mma16h(acc[0][2 * ntp],     A0, Bp.x, Bp.y);
                    mma16h(acc[1][2 * ntp],     A1, Bp.x, Bp.y);
                    mma16h(acc[0][2 * ntp + 1], A0, Bp.z, Bp.w);
                    mma16h(acc[1][2 * ntp + 1], A1, Bp.z, Bp.w);
                }
            }
        }
    }
    __syncthreads();   // ring + h1 frags fully consumed

    // --- G_a: W3F (-> dead ring) + ufA (-> dead XF+W1F) ---
    if (tid < 512) {
        cpa16(sb + OFF_W3F + tid * 16, gw + 139264 + tid * 16);
        cpa16(sb + OFF_UFA + tid * 16, (const char*)g_ufA + tid * 16);
    }
    cpcommit();
    // --- G_b: z (-> dead ring) + ufB ---
    {
        float* zs = (float*)(smc + OFF_ZS);
#pragma unroll
        for (int i = 0; i < 4; i++) {
            int idx = tid + i * 512;                // 2048 x float4
            int row = idx >> 5, c4 = (idx & 31) << 2;
            cpa16(smem_u32(&zs[row * 132 + c4]), &z[(size_t)(r0 + row) * ZD + c4]);
        }
        if (tid < 512) cpa16(sb + OFF_UFB + tid * 16, (const char*)g_ufB + tid * 16);
        cpcommit();
    }

    // epilogue -> h2 A-frags (overlay OFF_H1F), f16 bias+silu, paired STS.128
#pragma unroll
    for (int mt = 0; mt < 2; mt++) {
        int rb = wm * 2 + mt;
#pragma unroll
        for (int ntp = 0; ntp < 2; ntp++) {
            uint32_t bias0 = b2p[(wn * 4 + 2 * ntp) * 4 + q];
            uint32_t bias1 = b2p[(wn * 4 + 2 * ntp + 1) * 4 + q];
            int kk = wn * 2 + ntp;
            uint4 pk;
            pk.x = silu16(addh2(acc[mt][2 * ntp][0], bias0));
            pk.y = silu16(addh2(acc[mt][2 * ntp][1], bias0));
            pk.z = silu16(addh2(acc[mt][2 * ntp + 1][0], bias1));
            pk.w = silu16(addh2(acc[mt][2 * ntp + 1][1], bias1));
            *(uint4*)(smc + OFF_H1F + ((rb * 16 + kk) * 32 + lane) * 16) = pk;
        }
    }
    cpwait<1>();       // G_a (W3F + ufA) landed; G_b may fly
    __syncthreads();   // h2 frags + W3F visible

    // ================= GEMM3: h = h2 @ W3 (K-split 2 x N-split 2) ==========
    float* hp = (float*)(smc + OFF_HP);   // [2][64][20] fp32 partials
    {
        int rb = wid & 3, wk = (wid >> 2) & 1, nt3 = wid >> 3;
        float a3[4] = {0.f, 0.f, 0.f, 0.f};
#pragma unroll
        for (int ksl = 0; ksl < 8; ksl++) {
            int kk = wk * 8 + ksl;
            uint4 Av = *(const uint4*)(smc + OFF_H1F + ((rb * 16 + kk) * 32 + lane) * 16);
            uint32_t A[4] = {Av.x, Av.y, Av.z, Av.w};
            uint2 Bv = *(const uint2*)(smc + OFF_W3F + ((kk * 2 + nt3) * 32 + lane) * 8);
            uint32_t B[2] = {Bv.x, Bv.y};
            mma16(a3, A, B, a3);
        }
        int c0 = nt3 * 8 + 2 * q;
        *(float2*)&hp[(wk * 64 + rb * 16 + g) * 20 + c0]     = make_float2(a3[0], a3[1]);
        *(float2*)&hp[(wk * 64 + rb * 16 + g + 8) * 20 + c0] = make_float2(a3[2], a3[3]);
    }
    __syncthreads();   // hp published

    // ===== per-row epilogue: read hp -> regs, then write ds/lg (overlaps hp)
    float* ds = (float*)(smc + OFF_DS);
    float* lg = (float*)(smc + OFF_LG);
    float dreg[16];
    float lamg = 0.f;
    if (tid < 64) {
        int row = tid;
        float s[16], fro2 = 0.f;
#pragma unroll
        for (int r = 0; r < 16; r++) {
            float v = b3s[r] + hp[row * 20 + r] + hp[(64 + row) * 20 + r];
            float sr = 2.f / (1.f + __expf(-v));
            s[r] = sr;
            fro2 += sr * sr * cn2s[r];
        }
        float fro = sqrtf(fro2);
        float scale = fminf(2.2627416997969522f / fmaxf(fro, 1e-9f), 1.f);

        float v = dt_norm_g[r0 + row];
        if (isnan(v)) v = 0.f;
        v = fminf(fmaxf(v, 0.f), 1.f);
        float logdt = fminf(-3.f + v * 11.f, 2.7781512503836436f);   // log10(600)
        float dt = fmaxf(expf(logdt * 2.302585092994046f), 1e-30f);
        lamg = expf(-0.1f * dt);
#pragma unroll
        for (int r = 0; r < 16; r++) {
            float ss = s[r] * scale;
            dreg[r] = expf(-ss * ss * dt) * lamg - lamg;
        }
    }
    cpwait<0>();       // z + ufB landed
    __syncthreads();   // hp reads done -> safe to overwrite with ds/lg
    if (tid < 64) {
        lg[tid] = lamg;
#pragma unroll
        for (int r = 0; r < 16; r++) ds[tid * 20 + r] = dreg[r];
    }
    __syncthreads();   // ds/lg published

    const float* zs = (const float*)(smc + OFF_ZS);
    float* cs = (float*)(smc + OFF_CS);
    const char* ufA = smc + OFF_UFA;
    const char* ufB = smc + OFF_UFB;

    // ===== GEMM A: cs[row][r] = d[row][r] * (z @ U)[row][r]  (8 warps) =====
    if (wid < 8) {
        int mt = wid >> 1, nt = wid & 1;
        int rbase = mt * 16, cbase = nt * 8;
        float accA[4] = {0.f, 0.f, 0.f, 0.f};
#pragma unroll
        for (int kp = 0; kp < 8; kp++) {
            uint4 Bv = *(const uint4*)(ufA + ((kp * 2 + nt) * 32 + lane) * 16);
#pragma unroll
            for (int sub = 0; sub < 2; sub++) {
                int k0 = (kp * 2 + sub) * 8;
                uint32_t a[4] = {
                    fbits(zs[(rbase + g) * 132 + k0 + q]),
                    fbits(zs[(rbase + g + 8) * 132 + k0 + q]),
                    fbits(zs[(rbase + g) * 132 + k0 + q + 4]),
                    fbits(zs[(rbase + g + 8) * 132 + k0 + q + 4])};
                uint32_t b[2] = {sub ? Bv.z : Bv.x, sub ? Bv.w : Bv.y};
                mma8(accA, a, b, accA);
            }
        }
        int row0 = rbase + g, row1 = rbase + g + 8;
        int c0 = cbase + 2 * q, c1 = c0 + 1;
        cs[row0 * 20 + c0] = accA[0] * ds[row0 * 20 + c0];
        cs[row0 * 20 + c1] = accA[1] * ds[row0 * 20 + c1];
        cs[row1 * 20 + c0] = accA[2] * ds[row1 * 20 + c0];
        cs[row1 * 20 + c1] = accA[3] * ds[row1 * 20 + c1];
    }
    __syncthreads();   // cs published

    // ===== GEMM B + identity, direct to global (16 warps) =====
    {
        int mt = wid & 3, wnb = wid >> 2;     // mt: 16-row tile, wnb: 32-col group
        int rbase = mt * 16;
        float accB[4][4];
#pragma unroll
        for (int nt = 0; nt < 4; nt++)
#pragma unroll
            for (int i = 0; i < 4; i++) accB[nt][i] = 0.f;
#pragma unroll
        for (int ks = 0; ks < 2; ks++) {
            int k0 = ks * 8;
            uint32_t a[4] = {
                fbits(cs[(rbase + g) * 20 + k0 + q]),
                fbits(cs[(rbase + g + 8) * 20 + k0 + q]),
                fbits(cs[(rbase + g) * 20 + k0 + q + 4]),
                fbits(cs[(rbase + g + 8) * 20 + k0 + q + 4])};
#pragma unroll
            for (int ntp = 0; ntp < 2; ntp++) {
                uint4 Bp = *(const uint4*)(ufB + ((ks * 8 + wnb * 2 + ntp) * 32 + lane) * 16);
                uint32_t B0[2] = {Bp.x, Bp.y}, B1[2] = {Bp.z, Bp.w};
                mma8(accB[2 * ntp],     a, B0, accB[2 * ntp]);
                mma8(accB[2 * ntp + 1], a, B1, accB[2 * ntp + 1]);
            }
        }
        int row0 = rbase + g, row1 = rbase + g + 8;
        float l0 = lg[row0], l1 = lg[row1];
        size_t gr0 = (size_t)(r0 + row0) * ZD, gr1 = (size_t)(r0 + row1) * ZD;
#pragma unroll
        for (int nt = 0; nt < 4; nt++) {
            int cb = (wnb * 4 + nt) * 8;
            int c0 = cb + 2 * q;
            float2 z0 = *(const float2*)&zs[row0 * 132 + c0];
            float2 o0;
            o0.x = l0 * z0.x + accB[nt][0];
            o0.y = l0 * z0.y + accB[nt][1];
            *(float2*)&out[gr0 + c0] = o0;
            float2 z1 = *(const float2*)&zs[row1 * 132 + c0];
            float2 o1;
            o1.x = l1 * z1.x + accB[nt][2];
            o1.y = l1 * z1.y + accB[nt][3];
            *(float2*)&out[gr1 + c0] = o1;
        }
    }
}

extern "C" void kernel_launch(void* const* d_in, const int* in_sizes, int n_in,
                              void* d_out, int out_size) {
    const float* pt      = (const float*)d_in[0];
    const float* z       = (const float*)d_in[1];
    const float* dt_norm = (const float*)d_in[2];
    const float* base_U  = (const float*)d_in[3];
    const float* W1      = (const float*)d_in[4];
    const float* b1      = (const float*)d_in[5];
    const float* W2      = (const float*)d_in[6];
    const float* b2      = (const float*)d_in[7];
    const float* W3      = (const float*)d_in[8];
    const float* b3      = (const float*)d_in[9];
    float* out = (float*)d_out;

    cudaFuncSetAttribute(fused_kernel, cudaFuncAttributeMaxDynamicSharedMemorySize, SMEM_BYTES);

    prep_kernel<<<296, 256>>>(W1, W2, W3, base_U);
    fused_kernel<<<NBLK, 512, SMEM_BYTES>>>(pt, z, dt_norm, base_U, b1, b2, b3, out);
}